// round 5
// baseline (speedup 1.0000x reference)
#include <cuda_runtime.h>
#include <math.h>
#include <stdint.h>

#define NN    4096
#define EMBD  32
#define BQ    8192
#define KNN   20
#define FULL  0xffffffffu
#define RPC   64          // rows per CTA
#define RPW   8           // rows per warp
#define TILE  128
#define NTILES (NN / TILE)

typedef unsigned long long u64;
typedef unsigned int u32;

// Scratch (device globals; no allocation in kernel_launch)
__device__ float g_norm[2 * NN];
__device__ int   g_nbr_idx[2 * NN * KNN];
__device__ float g_nbr_d2[2 * NN * KNN];

// ---------------------------------------------------------------------------
// packed f32x2 helpers (Blackwell FFMA2 path — PTX only)
// ---------------------------------------------------------------------------
__device__ __forceinline__ u64 pack2(float lo, float hi) {
    u64 r;
    asm("mov.b64 %0, {%1, %2};" : "=l"(r) : "f"(lo), "f"(hi));
    return r;
}
__device__ __forceinline__ void unpack2(u64 v, float& lo, float& hi) {
    asm("mov.b64 {%0, %1}, %2;" : "=f"(lo), "=f"(hi) : "l"(v));
}
__device__ __forceinline__ void ffma2(u64& d, u64 a, u64 b) {
    asm("fma.rn.f32x2 %0, %1, %2, %0;" : "+l"(d) : "l"(a), "l"(b));
}

// ---------------------------------------------------------------------------
// key helpers. key = orderable(d2)<<32 | (NN-1-j): ties prefer larger j
// (matches stable ascending argsort window semantics of the reference).
// ---------------------------------------------------------------------------
__device__ __forceinline__ u32 ord32(float f) {
    u32 u = __float_as_uint(f);
    return u ^ ((u32)((int)u >> 31) | 0x80000000u);
}
__device__ __forceinline__ u64 make_key(float f, int j) {
    return ((u64)ord32(f) << 32) | (u32)(NN - 1 - j);
}
__device__ __forceinline__ float key_d2(u64 k) {
    u32 u = (u32)(k >> 32);
    return (u & 0x80000000u) ? __uint_as_float(u & 0x7fffffffu)
                             : __uint_as_float(~u);
}

// warp-uniform insert of broadcast key v into distributed sorted list (asc)
__device__ __forceinline__ void insert_bcast(u64 v, u64& list, u64& tau,
                                             int lane) {
    if (v < tau) {
        unsigned lt = __ballot_sync(FULL, list < v);
        int pos = __popc(lt);
        u64 up1 = __shfl_up_sync(FULL, list, 1);
        if (lane == pos)      list = v;
        else if (lane > pos)  list = up1;
        tau = __shfl_sync(FULL, list, 31);
    }
}

// per-lane key stream-insert
__device__ __forceinline__ void insert_round(u64 k, u64& list, u64& tau,
                                             int lane) {
    unsigned m = __ballot_sync(FULL, k < tau);
    while (m) {
        int s = __ffs(m) - 1; m &= m - 1;
        u64 v = __shfl_sync(FULL, k, s);
        insert_bcast(v, list, tau, lane);
    }
}

__device__ __forceinline__ void cswap(u64& a, u64& b) {
    u64 mn = (a < b) ? a : b;
    u64 mx = (a < b) ? b : a;
    a = mn; b = mx;
}

// ---------------------------------------------------------------------------
// ||e||^2 per row for both embedding tables (kept separate so na/nb numerics
// are bit-identical to the previously-passing pipeline)
// ---------------------------------------------------------------------------
__global__ void norms_kernel(const float* __restrict__ e1,
                             const float* __restrict__ e2) {
    int r = blockIdx.x * blockDim.x + threadIdx.x;
    if (r >= 2 * NN) return;
    const float* e = (r < NN) ? e1 : e2;
    int row = r & (NN - 1);
    const float4* p = reinterpret_cast<const float4*>(e + (size_t)row * EMBD);
    float s = 0.f;
#pragma unroll
    for (int i = 0; i < 8; i++) {
        float4 v = p[i];
        s += v.x * v.x + v.y * v.y + v.z * v.z + v.w * v.w;
    }
    g_norm[r] = s;
}

// ---------------------------------------------------------------------------
// Fused distances + top-KNN. Grid (64, 2): 64-row block x branch.
// 256 threads = 8 warps, each warp owns 8 rows for the full column sweep.
// Per tile: register-tiled fp32 FFMA2 microGEMM + register-resident select.
// ---------------------------------------------------------------------------
__global__ void fused_knn(const float* __restrict__ emb1,
                          const float* __restrict__ emb2) {
    const int branch = blockIdx.y;
    const float* emb = branch ? emb2 : emb1;
    const int tid = threadIdx.x;
    const int wid = tid >> 5, lane = tid & 31;
    const int rowbase = blockIdx.x * RPC + wid * RPW;

    __shared__ float A_s[RPC * EMBD];        // [row][k]
    __shared__ float B_s[EMBD][TILE + 4];    // [k][col]

    // stage A rows (64 x 32 = 512 float4, 2 per thread, coalesced)
    {
        const float4* src = reinterpret_cast<const float4*>(
            emb + (size_t)(blockIdx.x * RPC) * EMBD);
        float4* dst = reinterpret_cast<float4*>(A_s);
        dst[tid] = src[tid];
        dst[tid + 256] = src[tid + 256];
    }
    // stage B tile 0 (transpose [col][k] -> [k][col])
    {
        const float4* src = reinterpret_cast<const float4*>(emb);
#pragma unroll
        for (int i = 0; i < 4; i++) {
            int lin = tid * 4 + i;
            int col = lin >> 3, k4 = lin & 7;
            float4 v = src[col * 8 + k4];
            B_s[k4 * 4 + 0][col] = v.x; B_s[k4 * 4 + 1][col] = v.y;
            B_s[k4 * 4 + 2][col] = v.z; B_s[k4 * 4 + 3][col] = v.w;
        }
    }
    __syncthreads();

    const float* nrm = g_norm + branch * NN;
    float na[RPW];
#pragma unroll
    for (int r = 0; r < RPW; r++) na[r] = nrm[rowbase + r];

    u64 list[RPW], tau[RPW];

    for (int tile = 0; tile < NTILES; tile++) {
        const int j0 = tile * TILE;

        // prefetch next B tile into registers
        float4 pf[4];
        if (tile + 1 < NTILES) {
            const float4* src = reinterpret_cast<const float4*>(
                emb + (size_t)(j0 + TILE) * EMBD);
#pragma unroll
            for (int i = 0; i < 4; i++) {
                int lin = tid * 4 + i;
                pf[i] = src[(lin >> 3) * 8 + (lin & 7)];
            }
        }

        // nb for my 4 columns
        float4 nb4 = *reinterpret_cast<const float4*>(nrm + j0 + lane * 4);
        float nb[4] = {nb4.x, nb4.y, nb4.z, nb4.w};

        // microGEMM: 8 rows x 4 cols, K=32, sequential-k FFMA2
        u64 acc[RPW][2];
#pragma unroll
        for (int r = 0; r < RPW; r++) { acc[r][0] = 0ull; acc[r][1] = 0ull; }

#pragma unroll
        for (int kk = 0; kk < EMBD / 4; kk++) {
            u64 bp[4][2];
#pragma unroll
            for (int dk = 0; dk < 4; dk++) {
                float4 b4 = *reinterpret_cast<const float4*>(
                    &B_s[kk * 4 + dk][lane * 4]);
                bp[dk][0] = pack2(b4.x, b4.y);
                bp[dk][1] = pack2(b4.z, b4.w);
            }
#pragma unroll
            for (int r = 0; r < RPW; r++) {
                float4 a4 = *reinterpret_cast<const float4*>(
                    &A_s[(wid * RPW + r) * EMBD + kk * 4]);
                float av[4] = {a4.x, a4.y, a4.z, a4.w};
#pragma unroll
                for (int dk = 0; dk < 4; dk++) {
                    u64 ap = pack2(av[dk], av[dk]);
                    ffma2(acc[r][0], ap, bp[dk][0]);
                    ffma2(acc[r][1], ap, bp[dk][1]);
                }
            }
        }

        // epilogue + select per row (d2 kept in registers, never stored)
#pragma unroll
        for (int r = 0; r < RPW; r++) {
            const int row_g = rowbase + r;
            float d[4];
            unpack2(acc[r][0], d[0], d[1]);
            unpack2(acc[r][1], d[2], d[3]);
#pragma unroll
            for (int c = 0; c < 4; c++) {
                float dd = na[r] + nb[c] - 2.f * d[c];
                d[c] = (j0 + lane * 4 + c == row_g) ? 3.4e38f : dd;
            }

            if (tile == 0) {
                // build 4 keys, sort them, init distributed list from minima
                u64 k0 = make_key(d[0], j0 + lane * 4 + 0);
                u64 k1 = make_key(d[1], j0 + lane * 4 + 1);
                u64 k2 = make_key(d[2], j0 + lane * 4 + 2);
                u64 k3 = make_key(d[3], j0 + lane * 4 + 3);
                cswap(k0, k1); cswap(k2, k3);
                cswap(k0, k2); cswap(k1, k3); cswap(k1, k2);
                u64 L = k0;
                // bitonic sort 32 keys ascending across lanes (verified)
#pragma unroll
                for (int k = 2; k <= 32; k <<= 1) {
#pragma unroll
                    for (int j = k >> 1; j > 0; j >>= 1) {
                        u64 o = __shfl_xor_sync(FULL, L, j);
                        bool up = ((lane & k) == 0) || (k == 32);
                        bool lower = ((lane & j) == 0);
                        bool take_min = (lower == up);
                        u64 mn = (o < L) ? o : L;
                        u64 mx = (o < L) ? L : o;
                        L = take_min ? mn : mx;
                    }
                }
                u64 T = __shfl_sync(FULL, L, 31);
                insert_round(k1, L, T, lane);   // stream remaining elements
                insert_round(k2, L, T, lane);
                insert_round(k3, L, T, lane);
                list[r] = L; tau[r] = T;
            } else {
                float mn = fminf(fminf(d[0], d[1]), fminf(d[2], d[3]));
                float taud = key_d2(tau[r]);
                unsigned trig = __ballot_sync(FULL, mn <= taud);
                if (trig) {
                    u64 L = list[r], T = tau[r];
                    do {
                        int s = __ffs(trig) - 1; trig &= trig - 1;
                        int jb = j0 + s * 4;
#pragma unroll
                        for (int c = 0; c < 4; c++) {
                            float dc = __shfl_sync(FULL, d[c], s);
                            insert_bcast(make_key(dc, jb + c), L, T, lane);
                        }
                    } while (trig);
                    list[r] = L; tau[r] = T;
                }
            }
        }

        __syncthreads();
        if (tile + 1 < NTILES) {
#pragma unroll
            for (int i = 0; i < 4; i++) {
                int lin = tid * 4 + i;
                int col = lin >> 3, k4 = lin & 7;
                B_s[k4 * 4 + 0][col] = pf[i].x; B_s[k4 * 4 + 1][col] = pf[i].y;
                B_s[k4 * 4 + 2][col] = pf[i].z; B_s[k4 * 4 + 3][col] = pf[i].w;
            }
            __syncthreads();
        }
    }

    // write per-row top-20 (lanes 0..19 hold smallest keys ascending)
#pragma unroll
    for (int r = 0; r < RPW; r++) {
        if (lane < KNN) {
            int o = (branch * NN + rowbase + r) * KNN + lane;
            g_nbr_idx[o] = NN - 1 - (int)(u32)list[r];
            g_nbr_d2[o]  = key_d2(list[r]);
        }
    }
}

// ---------------------------------------------------------------------------
// Per-query gather + features + MLP. One warp per query.
// ---------------------------------------------------------------------------
__device__ __forceinline__ float warp_sum(float v) {
#pragma unroll
    for (int off = 16; off > 0; off >>= 1)
        v += __shfl_xor_sync(FULL, v, off);
    return v;
}

__global__ void gather_mlp(const int* __restrict__ timev,
                           const int* __restrict__ idx1v,
                           const int* __restrict__ idx2v,
                           const float* __restrict__ residuals,
                           const float* __restrict__ means,
                           const float* __restrict__ stds,
                           const float* __restrict__ W1,
                           const float* __restrict__ b1,
                           const float* __restrict__ Wm,
                           const float* __restrict__ bm,
                           const float* __restrict__ Ws,
                           const float* __restrict__ bs,
                           float* __restrict__ out) {
    int q = (blockIdx.x * blockDim.x + threadIdx.x) >> 5;
    int lane = threadIdx.x & 31;
    if (q >= BQ) return;

    int t = timev[q], a = idx1v[q], c = idx2v[q];
    size_t base = (size_t)t * NN * NN;

    float f[8];
#pragma unroll
    for (int br = 0; br < 2; ++br) {
        int row = br ? c : a;
        float wgt = 0.f, sel = 0.f;
        if (lane < KNN) {
            int o = (br * NN + row) * KNN + lane;
            int j = g_nbr_idx[o];
            float d2 = g_nbr_d2[o];
            float sim = sqrtf(fmaxf(d2, 0.f)) + 0.001f;
            wgt = expf(-sim);
            sel = br ? residuals[base + (size_t)a * NN + j]     // f2: row context
                     : residuals[base + (size_t)j * NN + c];    // f1: column context
        }
        float sw  = warp_sum(wgt * sel);
        float wsm = warp_sum(wgt);
        float ss  = warp_sum(sel);
        float s2  = warp_sum(sel * sel);
        f[br * 3 + 0] = sw / wsm;
        f[br * 3 + 1] = wsm;
        f[br * 3 + 2] = sqrtf(fmaxf((s2 - ss * ss / (float)KNN) / (float)(KNN - 1), 0.f));
    }
    f[6] = means[base + (size_t)a * NN + c];
    f[7] = stds[base + (size_t)a * NN + c];

    float om = 0.f, osum = 0.f;
#pragma unroll
    for (int r = 0; r < 2; r++) {
        int k = lane + r * 32;
        float h = b1[k];
#pragma unroll
        for (int ff = 0; ff < 8; ++ff) h = fmaf(f[ff], W1[k * 8 + ff], h);
        h = fmaxf(h, 0.f);
        om   = fmaf(h, Wm[k], om);
        osum = fmaf(h, Ws[k], osum);
    }
    om = warp_sum(om);
    osum = warp_sum(osum);
    if (lane == 0) {
        out[q]      = om   + bm[0];
        out[BQ + q] = osum + bs[0];
    }
}

// ---------------------------------------------------------------------------
extern "C" void kernel_launch(void* const* d_in, const int* in_sizes, int n_in,
                              void* d_out, int out_size) {
    const int*   timev = (const int*)d_in[0];
    const int*   idx1  = (const int*)d_in[1];
    const int*   idx2  = (const int*)d_in[2];
    const float* resid = (const float*)d_in[3];
    const float* means = (const float*)d_in[4];
    const float* stds  = (const float*)d_in[5];
    const float* emb1  = (const float*)d_in[6];
    const float* emb2  = (const float*)d_in[7];
    const float* W1    = (const float*)d_in[8];
    const float* b1    = (const float*)d_in[9];
    const float* Wm    = (const float*)d_in[10];
    const float* bm    = (const float*)d_in[11];
    const float* Ws    = (const float*)d_in[12];
    const float* bs    = (const float*)d_in[13];
    float* out = (float*)d_out;

    norms_kernel<<<32, 256>>>(emb1, emb2);

    dim3 g(NN / RPC, 2);                   // 64 row-blocks x 2 branches
    fused_knn<<<g, 256>>>(emb1, emb2);

    gather_mlp<<<BQ / 8, 256>>>(timev, idx1, idx2, resid, means, stds,
                                W1, b1, Wm, bm, Ws, bs, out);
}

// round 6
// speedup vs baseline: 1.9400x; 1.9400x over previous
#include <cuda_runtime.h>
#include <math.h>
#include <stdint.h>

#define NN   4096
#define EMBD 32
#define BQ   8192
#define KNN  20
#define FULL 0xffffffffu

typedef unsigned long long u64;
typedef unsigned int u32;

// Scratch (device globals; no allocation in kernel_launch)
__device__ float g_D2[(size_t)NN * NN];        // 64 MB, reused per branch
__device__ float g_norm[2 * NN];
__device__ int   g_nbr_idx[2 * NN * KNN];
__device__ float g_nbr_d2[2 * NN * KNN];

// ---------------------------------------------------------------------------
// packed f32x2 helpers (Blackwell FFMA2 path — PTX only)
// ---------------------------------------------------------------------------
__device__ __forceinline__ u64 pack2(float lo, float hi) {
    u64 r;
    asm("mov.b64 %0, {%1, %2};" : "=l"(r) : "f"(lo), "f"(hi));
    return r;
}
__device__ __forceinline__ void unpack2(u64 v, float& lo, float& hi) {
    asm("mov.b64 {%0, %1}, %2;" : "=f"(lo), "=f"(hi) : "l"(v));
}
__device__ __forceinline__ void ffma2(u64& d, u64 a, u64 b) {
    asm("fma.rn.f32x2 %0, %1, %2, %0;" : "+l"(d) : "l"(a), "l"(b));
}

// ---------------------------------------------------------------------------
// ||e||^2 per row for both embedding tables
// ---------------------------------------------------------------------------
__global__ void norms_kernel(const float* __restrict__ e1,
                             const float* __restrict__ e2) {
    int r = blockIdx.x * blockDim.x + threadIdx.x;
    if (r >= 2 * NN) return;
    const float* e = (r < NN) ? e1 : e2;
    int row = r & (NN - 1);
    const float4* p = reinterpret_cast<const float4*>(e + (size_t)row * EMBD);
    float s = 0.f;
#pragma unroll
    for (int i = 0; i < 8; i++) {
        float4 v = p[i];
        s += v.x * v.x + v.y * v.y + v.z * v.z + v.w * v.w;
    }
    g_norm[r] = s;
}

// ---------------------------------------------------------------------------
// All-pairs squared distances, one branch. Full grid, coalesced stores only.
// fp32, 128x128 tile per CTA, 8x8 per thread, K=32 slab, FFMA2 inner loop.
// (R4 kernel verbatim — measured 33.0us)
// ---------------------------------------------------------------------------
__global__ void __launch_bounds__(256, 2) knn_gemm(const float* __restrict__ emb,
                                                   int branch) {
    __shared__ float As[EMBD][132];
    __shared__ float Bs[EMBD][132];

    const int tid = threadIdx.x;          // 256 threads
    const int tx = tid & 15, ty = tid >> 4;
    const int i0 = blockIdx.y * 128, j0 = blockIdx.x * 128;

    const float4* ea = reinterpret_cast<const float4*>(emb) + (size_t)i0 * 8;
    const float4* eb = reinterpret_cast<const float4*>(emb) + (size_t)j0 * 8;

#pragma unroll
    for (int l = 0; l < 4; l++) {
        int lin = l * 256 + tid;          // 1024 float4s = 128 rows x 8
        int row = lin >> 3, c4 = lin & 7;
        float4 va = ea[row * 8 + c4];
        As[c4 * 4 + 0][row] = va.x; As[c4 * 4 + 1][row] = va.y;
        As[c4 * 4 + 2][row] = va.z; As[c4 * 4 + 3][row] = va.w;
        float4 vb = eb[row * 8 + c4];
        Bs[c4 * 4 + 0][row] = vb.x; Bs[c4 * 4 + 1][row] = vb.y;
        Bs[c4 * 4 + 2][row] = vb.z; Bs[c4 * 4 + 3][row] = vb.w;
    }
    __syncthreads();

    u64 accp[8][4];                       // 8 rows x 4 col-pairs, packed f32x2
#pragma unroll
    for (int r = 0; r < 8; r++)
#pragma unroll
        for (int c = 0; c < 4; c++) accp[r][c] = 0ull;

#pragma unroll
    for (int k = 0; k < EMBD; k++) {
        float a_[8], b_[8];
        *reinterpret_cast<float4*>(&a_[0]) = *reinterpret_cast<const float4*>(&As[k][ty * 8]);
        *reinterpret_cast<float4*>(&a_[4]) = *reinterpret_cast<const float4*>(&As[k][ty * 8 + 4]);
        *reinterpret_cast<float4*>(&b_[0]) = *reinterpret_cast<const float4*>(&Bs[k][tx * 8]);
        *reinterpret_cast<float4*>(&b_[4]) = *reinterpret_cast<const float4*>(&Bs[k][tx * 8 + 4]);
        u64 bp[4];
#pragma unroll
        for (int c = 0; c < 4; c++) bp[c] = pack2(b_[2 * c], b_[2 * c + 1]);
#pragma unroll
        for (int r = 0; r < 8; r++) {
            u64 as_ = pack2(a_[r], a_[r]);
#pragma unroll
            for (int c = 0; c < 4; c++) ffma2(accp[r][c], as_, bp[c]);
        }
    }

    const float* nrm = g_norm + branch * NN;
    float nb[8];
#pragma unroll
    for (int c = 0; c < 8; c++) nb[c] = nrm[j0 + tx * 8 + c];

#pragma unroll
    for (int r = 0; r < 8; r++) {
        int gi = i0 + ty * 8 + r;
        float na = nrm[gi];
        float o[8];
#pragma unroll
        for (int c = 0; c < 4; c++) unpack2(accp[r][c], o[2 * c], o[2 * c + 1]);
#pragma unroll
        for (int c = 0; c < 8; c++) {
            int gj = j0 + tx * 8 + c;
            float d = na + nb[c] - 2.f * o[c];
            o[c] = (gi == gj) ? 3.4e38f : d;
        }
        float* dst = g_D2 + (size_t)gi * NN + j0 + tx * 8;
        *reinterpret_cast<float4*>(dst)     = make_float4(o[0], o[1], o[2], o[3]);
        *reinterpret_cast<float4*>(dst + 4) = make_float4(o[4], o[5], o[6], o[7]);
    }
}

// ---------------------------------------------------------------------------
// Selection. key = orderable(d2)<<32 | (NN-1-j): ties prefer larger j
// (matches stable ascending argsort window semantics of the reference).
// Warp-distributed sorted list, one u64 key per lane; only the first KNN
// entries are "live" — tau is lane KNN-1's key. Common path per element is
// one float compare + one ballot; exact u64 check inside the broadcast path.
// ---------------------------------------------------------------------------
__device__ __forceinline__ u32 ord32(float f) {
    u32 u = __float_as_uint(f);
    return u ^ ((u32)((int)u >> 31) | 0x80000000u);
}
__device__ __forceinline__ u64 make_key(float f, int j) {
    return ((u64)ord32(f) << 32) | (u32)(NN - 1 - j);
}
__device__ __forceinline__ float key_d2(u64 k) {
    u32 u = (u32)(k >> 32);
    return (u & 0x80000000u) ? __uint_as_float(u & 0x7fffffffu)
                             : __uint_as_float(~u);
}

// stream one element (per-lane value d at column it*128 + lane*4 + e)
__device__ __forceinline__ void stream_elem(float d, int it, int e,
                                            u64& list, u64& tau,
                                            float& tau_d2, int lane) {
    unsigned m = __ballot_sync(FULL, d <= tau_d2);   // superset of key<tau
    while (m) {
        int s = __ffs(m) - 1; m &= m - 1;
        float dv = __shfl_sync(FULL, d, s);
        u64 key = make_key(dv, it * 128 + s * 4 + e);
        if (key < tau) {                              // exact check
            unsigned lt = __ballot_sync(FULL, list < key);
            u64 up1 = __shfl_up_sync(FULL, list, 1);  // independent of ballot
            int pos = __popc(lt);                     // pos <= KNN-1 guaranteed
            if (lane == pos)      list = key;
            else if (lane > pos)  list = up1;
            tau = __shfl_sync(FULL, list, KNN - 1);
            tau_d2 = key_d2(tau);
        }
    }
}

__global__ void knn_select(int branch) {
    int gw = blockIdx.x * (blockDim.x >> 5) + (threadIdx.x >> 5);
    int lane = threadIdx.x & 31;
    if (gw >= NN) return;

    const float4* row = reinterpret_cast<const float4*>(g_D2 + (size_t)gw * NN);

    // init list from elements j = lane*4 of the first 128-element batch
    float4 v = row[lane];
    u64 list = make_key(v.x, lane * 4);

    // bitonic sort 32 keys ascending across lanes (verified)
#pragma unroll
    for (int k = 2; k <= 32; k <<= 1) {
#pragma unroll
        for (int j = k >> 1; j > 0; j >>= 1) {
            u64 o = __shfl_xor_sync(FULL, list, j);
            bool up = ((lane & k) == 0) || (k == 32);
            bool lower = ((lane & j) == 0);
            bool take_min = (lower == up);
            u64 mn = (o < list) ? o : list;
            u64 mx = (o < list) ? list : o;
            list = take_min ? mn : mx;
        }
    }
    u64 tau = __shfl_sync(FULL, list, KNN - 1);       // 20th smallest so far
    float tau_d2 = key_d2(tau);

    // remaining components of the first batch
    stream_elem(v.y, 0, 1, list, tau, tau_d2, lane);
    stream_elem(v.z, 0, 2, list, tau, tau_d2, lane);
    stream_elem(v.w, 0, 3, list, tau, tau_d2, lane);

    // main scan: per element 1 FSETP + 1 ballot on the common path
    for (int it = 1; it < NN / 128; ++it) {
        v = row[it * 32 + lane];
        stream_elem(v.x, it, 0, list, tau, tau_d2, lane);
        stream_elem(v.y, it, 1, list, tau, tau_d2, lane);
        stream_elem(v.z, it, 2, list, tau, tau_d2, lane);
        stream_elem(v.w, it, 3, list, tau, tau_d2, lane);
    }

    // lanes 0..19 hold the top-20 (ascending d2); decode and store
    if (lane < KNN) {
        int o = (branch * NN + gw) * KNN + lane;
        g_nbr_idx[o] = NN - 1 - (int)(u32)list;
        g_nbr_d2[o] = key_d2(list);
    }
}

// ---------------------------------------------------------------------------
// Per-query gather + features + MLP. One warp per query.
// ---------------------------------------------------------------------------
__device__ __forceinline__ float warp_sum(float v) {
#pragma unroll
    for (int off = 16; off > 0; off >>= 1)
        v += __shfl_xor_sync(FULL, v, off);
    return v;
}

__global__ void gather_mlp(const int* __restrict__ timev,
                           const int* __restrict__ idx1v,
                           const int* __restrict__ idx2v,
                           const float* __restrict__ residuals,
                           const float* __restrict__ means,
                           const float* __restrict__ stds,
                           const float* __restrict__ W1,
                           const float* __restrict__ b1,
                           const float* __restrict__ Wm,
                           const float* __restrict__ bm,
                           const float* __restrict__ Ws,
                           const float* __restrict__ bs,
                           float* __restrict__ out) {
    int q = (blockIdx.x * blockDim.x + threadIdx.x) >> 5;
    int lane = threadIdx.x & 31;
    if (q >= BQ) return;

    int t = timev[q], a = idx1v[q], c = idx2v[q];
    size_t base = (size_t)t * NN * NN;

    float f[8];
#pragma unroll
    for (int br = 0; br < 2; ++br) {
        int row = br ? c : a;
        float wgt = 0.f, sel = 0.f;
        if (lane < KNN) {
            int o = (br * NN + row) * KNN + lane;
            int j = g_nbr_idx[o];
            float d2 = g_nbr_d2[o];
            float sim = sqrtf(fmaxf(d2, 0.f)) + 0.001f;
            wgt = expf(-sim);
            sel = br ? residuals[base + (size_t)a * NN + j]     // f2: row context
                     : residuals[base + (size_t)j * NN + c];    // f1: column context
        }
        float sw  = warp_sum(wgt * sel);
        float wsm = warp_sum(wgt);
        float ss  = warp_sum(sel);
        float s2  = warp_sum(sel * sel);
        f[br * 3 + 0] = sw / wsm;
        f[br * 3 + 1] = wsm;
        f[br * 3 + 2] = sqrtf(fmaxf((s2 - ss * ss / (float)KNN) / (float)(KNN - 1), 0.f));
    }
    f[6] = means[base + (size_t)a * NN + c];
    f[7] = stds[base + (size_t)a * NN + c];

    float om = 0.f, osum = 0.f;
#pragma unroll
    for (int r = 0; r < 2; r++) {
        int k = lane + r * 32;
        float h = b1[k];
#pragma unroll
        for (int ff = 0; ff < 8; ++ff) h = fmaf(f[ff], W1[k * 8 + ff], h);
        h = fmaxf(h, 0.f);
        om   = fmaf(h, Wm[k], om);
        osum = fmaf(h, Ws[k], osum);
    }
    om = warp_sum(om);
    osum = warp_sum(osum);
    if (lane == 0) {
        out[q]      = om   + bm[0];
        out[BQ + q] = osum + bs[0];
    }
}

// ---------------------------------------------------------------------------
extern "C" void kernel_launch(void* const* d_in, const int* in_sizes, int n_in,
                              void* d_out, int out_size) {
    const int*   timev = (const int*)d_in[0];
    const int*   idx1  = (const int*)d_in[1];
    const int*   idx2  = (const int*)d_in[2];
    const float* resid = (const float*)d_in[3];
    const float* means = (const float*)d_in[4];
    const float* stds  = (const float*)d_in[5];
    const float* emb1  = (const float*)d_in[6];
    const float* emb2  = (const float*)d_in[7];
    const float* W1    = (const float*)d_in[8];
    const float* b1    = (const float*)d_in[9];
    const float* Wm    = (const float*)d_in[10];
    const float* bm    = (const float*)d_in[11];
    const float* Ws    = (const float*)d_in[12];
    const float* bs    = (const float*)d_in[13];
    float* out = (float*)d_out;

    norms_kernel<<<32, 256>>>(emb1, emb2);

    dim3 gg(NN / 128, NN / 128);
    // branch 0 (emb1)
    knn_gemm<<<gg, 256>>>(emb1, 0);
    knn_select<<<NN / 8, 256>>>(0);
    // branch 1 (emb2)
    knn_gemm<<<gg, 256>>>(emb2, 1);
    knn_select<<<NN / 8, 256>>>(1);

    gather_mlp<<<BQ / 8, 256>>>(timev, idx1, idx2, resid, means, stds,
                                W1, b1, Wm, bm, Ws, bs, out);
}